// round 4
// baseline (speedup 1.0000x reference)
#include <cuda_runtime.h>
#include <cuda_bf16.h>

// ---------------------------------------------------------------------------
// phi_{b,v}(d) = sum_r pref_r[b,v] * exp(-0.5/w_r^2 * (d - o_r)^2)
// tabulated per (b,v) as piecewise quadratics in GLOBAL form:
//   phi(d) ~= A_k + B_k*d + C_k*d^2   for d in [k*h, (k+1)*h)
// ---------------------------------------------------------------------------
#define KNOTS   512
#define DMAXF   16.0f
#define SLICES  4
#define KS      (KNOTS / SLICES)   // 128 intervals per build block

__device__ float4 g_table[2 * 128 * KNOTS];   // [B*MAXZ, KNOTS]

__device__ __forceinline__ float ex2f_fast(float x) {
    float y; asm("ex2.approx.ftz.f32 %0, %1;" : "=f"(y) : "f"(x)); return y;
}
__device__ __forceinline__ float sqrtf_fast(float x) {
    float y; asm("sqrt.approx.f32 %0, %1;" : "=f"(y) : "f"(x)); return y;
}

// ---------------------------------------------------------------------------
// Kernel 1 (fused): prefactor + table build.
// grid = (B*MAXZ)*SLICES blocks, 256 threads.
//  phase 1: sx[a] = emb[v,a] * time-rbf(t_b, a)              (threads < A)
//  phase 2: pref[r] = sum_a sx[a] * W[a,r]                   (threads < R)
//  phase 3: sample phi at 2*KS+1 points of this slice (50 exps each)
//  phase 4: fit per-interval quadratic, convert to global form, store.
// ---------------------------------------------------------------------------
template <int RR>
__global__ __launch_bounds__(256)
void build_all_kernel(const float* __restrict__ t,
                      const float* __restrict__ emb,
                      const float* __restrict__ W,
                      const float* __restrict__ r_off,
                      const float* __restrict__ r_wid,
                      const float* __restrict__ t_off,
                      const float* __restrict__ t_wid,
                      int A, int R, int MAXZ) {
    __shared__ float sx[128];
    __shared__ float s_pref[64], s_k2[64], s_off[64];
    __shared__ float s_phi[2 * KS + 1];

    const float LOG2E = 1.4426950408889634f;
    int pv    = blockIdx.x / SLICES;
    int slice = blockIdx.x % SLICES;
    int b     = pv / MAXZ;
    int v     = pv % MAXZ;
    int tid   = threadIdx.x;
    int Ruse  = (RR > 0) ? RR : R;

    if (tid < A) {
        float tw = t_wid[tid];
        float dt = t[b] - t_off[tid];
        float c  = (-0.5f / (tw * tw)) * LOG2E;
        sx[tid] = emb[(size_t)v * A + tid] * ex2f_fast(c * dt * dt);
    }
    if (tid < Ruse) {
        float w = r_wid[tid];
        s_k2[tid]  = (-0.5f / (w * w)) * LOG2E;
        s_off[tid] = r_off[tid];
    }
    __syncthreads();

    if (tid < Ruse) {
        float s0 = 0.f, s1 = 0.f, s2 = 0.f, s3 = 0.f;
        int a = 0;
        for (; a + 3 < A; a += 4) {
            s0 = fmaf(sx[a + 0], __ldg(&W[(size_t)(a + 0) * R + tid]), s0);
            s1 = fmaf(sx[a + 1], __ldg(&W[(size_t)(a + 1) * R + tid]), s1);
            s2 = fmaf(sx[a + 2], __ldg(&W[(size_t)(a + 2) * R + tid]), s2);
            s3 = fmaf(sx[a + 3], __ldg(&W[(size_t)(a + 3) * R + tid]), s3);
        }
        for (; a < A; a++) s0 = fmaf(sx[a], __ldg(&W[(size_t)a * R + tid]), s0);
        s_pref[tid] = (s0 + s1) + (s2 + s3);
    }
    __syncthreads();

    const float hh = DMAXF / (float)KNOTS;
    int base = slice * KS;
    for (int p = tid; p < 2 * KS + 1; p += 256) {
        float d = (float)(base * 2 + p) * (0.5f * hh);
        float acc = 0.0f;
        if (RR > 0) {
#pragma unroll
            for (int r = 0; r < RR; r++) {
                float dd = d - s_off[r];
                acc = fmaf(s_pref[r], ex2f_fast(s_k2[r] * dd * dd), acc);
            }
        } else {
            for (int r = 0; r < R; r++) {
                float dd = d - s_off[r];
                acc = fmaf(s_pref[r], ex2f_fast(s_k2[r] * dd * dd), acc);
            }
        }
        s_phi[p] = acc;
    }
    __syncthreads();

    if (tid < KS) {
        float y0 = s_phi[2 * tid + 0];
        float ym = s_phi[2 * tid + 1];
        float y1 = s_phi[2 * tid + 2];
        float inv_h = 1.0f / hh;
        int   k  = base + tid;
        float d0 = (float)k * hh;
        // local:  y0 + bl*u + cl*u^2,  u = d - d0
        float bl = (4.0f * ym - 3.0f * y0 - y1) * inv_h;
        float cl = 2.0f * (y1 - 2.0f * ym + y0) * (inv_h * inv_h);
        // global: A + B*d + C*d^2
        float Cg = cl;
        float Bg = bl - 2.0f * cl * d0;
        float Ag = y0 - bl * d0 + cl * d0 * d0;
        g_table[(size_t)pv * KNOTS + k] = make_float4(Ag, Bg, Cg, 0.0f);
    }
}

// ---------------------------------------------------------------------------
// Kernel 2: main pairwise kernel. 128 threads; each block handles TWO rows
// (i0, i0 + ceil(N/2)) of one batch, sharing staged packed-float3 positions.
// Per pair per row: 3 sub, 3 fma (eps folded), rsq->sqrt, idx, LDG.128 (L1),
// 2 fma eval, 3 fma accumulate.
// ---------------------------------------------------------------------------
__global__ __launch_bounds__(128)
void vf_main_kernel(const float* __restrict__ pos,
                    const int*   __restrict__ z,
                    float*       __restrict__ out,
                    int N, int MAXZ) {
    extern __shared__ float s_pos[];   // [3N] packed float3
    __shared__ float s_red[24];

    int halfN = (N + 1) >> 1;
    int b  = blockIdx.x / halfN;
    int i0 = blockIdx.x % halfN;
    int i1 = i0 + halfN;
    bool has1 = (i1 < N);
    int tid = threadIdx.x;

    const float* posb = pos + (size_t)b * N * 3;
    // vectorized staging: 3N floats as float4 chunks (+ scalar tail)
    int nvec = (3 * N) >> 2;
    const float4* posb4 = (const float4*)posb;
    for (int idx = tid; idx < nvec; idx += 128)
        ((float4*)s_pos)[idx] = __ldg(&posb4[idx]);
    for (int idx = 4 * nvec + tid; idx < 3 * N; idx += 128)
        s_pos[idx] = posb[idx];

    const float4* tab0 = g_table + (size_t)(b * MAXZ + z[i0]) * KNOTS;
    const float4* tab1 = has1 ? (g_table + (size_t)(b * MAXZ + z[i1]) * KNOTS)
                              : tab0;
    __syncthreads();

    float p0x = s_pos[3 * i0 + 0], p0y = s_pos[3 * i0 + 1], p0z = s_pos[3 * i0 + 2];
    float p1x, p1y, p1z;
    if (has1) { p1x = s_pos[3 * i1 + 0]; p1y = s_pos[3 * i1 + 1]; p1z = s_pos[3 * i1 + 2]; }
    else      { p1x = p0x; p1y = p0y; p1z = p0z; }

    const float inv_h  = (float)KNOTS / DMAXF;
    const float dclamp = DMAXF - 0.5f * (DMAXF / (float)KNOTS);

    float a00 = 0.f, a01 = 0.f, a02 = 0.f;
    float a10 = 0.f, a11 = 0.f, a12 = 0.f;

#pragma unroll 4
    for (int j = tid; j < N; j += 128) {
        float pjx = s_pos[3 * j + 0];
        float pjy = s_pos[3 * j + 1];
        float pjz = s_pos[3 * j + 2];
        {
            float rx = p0x - pjx, ry = p0y - pjy, rz = p0z - pjz;
            float d2 = fmaf(rx, rx, fmaf(ry, ry, fmaf(rz, rz, 1e-6f)));
            float d  = fminf(sqrtf_fast(d2), dclamp);
            int   k  = (int)(d * inv_h);
            float4 c = __ldg(&tab0[k]);
            float phi = fmaf(fmaf(c.z, d, c.y), d, c.x);
            a00 = fmaf(phi, rx, a00);
            a01 = fmaf(phi, ry, a01);
            a02 = fmaf(phi, rz, a02);
        }
        {
            float rx = p1x - pjx, ry = p1y - pjy, rz = p1z - pjz;
            float d2 = fmaf(rx, rx, fmaf(ry, ry, fmaf(rz, rz, 1e-6f)));
            float d  = fminf(sqrtf_fast(d2), dclamp);
            int   k  = (int)(d * inv_h);
            float4 c = __ldg(&tab1[k]);
            float phi = fmaf(fmaf(c.z, d, c.y), d, c.x);
            a10 = fmaf(phi, rx, a10);
            a11 = fmaf(phi, ry, a11);
            a12 = fmaf(phi, rz, a12);
        }
    }

#pragma unroll
    for (int off = 16; off > 0; off >>= 1) {
        a00 += __shfl_down_sync(0xFFFFFFFFu, a00, off);
        a01 += __shfl_down_sync(0xFFFFFFFFu, a01, off);
        a02 += __shfl_down_sync(0xFFFFFFFFu, a02, off);
        a10 += __shfl_down_sync(0xFFFFFFFFu, a10, off);
        a11 += __shfl_down_sync(0xFFFFFFFFu, a11, off);
        a12 += __shfl_down_sync(0xFFFFFFFFu, a12, off);
    }
    int warp = tid >> 5, lane = tid & 31;
    if (lane == 0) {
        s_red[warp * 6 + 0] = a00; s_red[warp * 6 + 1] = a01;
        s_red[warp * 6 + 2] = a02; s_red[warp * 6 + 3] = a10;
        s_red[warp * 6 + 4] = a11; s_red[warp * 6 + 5] = a12;
    }
    __syncthreads();
    if (tid == 0) {
        float r0 = 0.f, r1 = 0.f, r2 = 0.f, r3 = 0.f, r4 = 0.f, r5 = 0.f;
#pragma unroll
        for (int w = 0; w < 4; w++) {
            r0 += s_red[w * 6 + 0]; r1 += s_red[w * 6 + 1];
            r2 += s_red[w * 6 + 2]; r3 += s_red[w * 6 + 3];
            r4 += s_red[w * 6 + 4]; r5 += s_red[w * 6 + 5];
        }
        size_t o0 = ((size_t)b * N + i0) * 3;
        out[o0 + 0] = r0 + p0x;
        out[o0 + 1] = r1 + p0y;
        out[o0 + 2] = r2 + p0z;
        if (has1) {
            size_t o1 = ((size_t)b * N + i1) * 3;
            out[o1 + 0] = r3 + p1x;
            out[o1 + 1] = r4 + p1y;
            out[o1 + 2] = r5 + p1z;
        }
    }
}

// ---------------------------------------------------------------------------
// Inputs (metadata order):
//  0 positions [B,N,3] f32, 1 t [B] f32, 2 z [N] i32, 3 emb [MAXZ,A] f32,
//  4 W [A,R] f32, 5 rad_off [R], 6 rad_wid [R], 7 time_off [A], 8 time_wid [A]
// ---------------------------------------------------------------------------
extern "C" void kernel_launch(void* const* d_in, const int* in_sizes, int n_in,
                              void* d_out, int out_size) {
    const float* positions = (const float*)d_in[0];
    const float* t         = (const float*)d_in[1];
    const int*   z         = (const int*)  d_in[2];
    const float* emb       = (const float*)d_in[3];
    const float* W         = (const float*)d_in[4];
    const float* r_off     = (const float*)d_in[5];
    const float* r_wid     = (const float*)d_in[6];
    const float* t_off     = (const float*)d_in[7];
    const float* t_wid     = (const float*)d_in[8];

    int B    = in_sizes[1];
    int N    = in_sizes[2];
    int R    = in_sizes[5];
    int A    = in_sizes[7];
    int MAXZ = in_sizes[3] / A;

    if (R == 50)
        build_all_kernel<50><<<B * MAXZ * SLICES, 256>>>(
            t, emb, W, r_off, r_wid, t_off, t_wid, A, R, MAXZ);
    else
        build_all_kernel<0><<<B * MAXZ * SLICES, 256>>>(
            t, emb, W, r_off, r_wid, t_off, t_wid, A, R, MAXZ);

    int halfN = (N + 1) >> 1;
    size_t smem = (size_t)3 * N * sizeof(float);
    vf_main_kernel<<<B * halfN, 128, smem>>>(positions, z, (float*)d_out,
                                             N, MAXZ);
}